// round 3
// baseline (speedup 1.0000x reference)
#include <cuda_runtime.h>
#include <math.h>
#include <stdint.h>

#define Bsz 256
#define Ssz 2048
#define Dsz 64
#define Hsz 256
#define NCTA 128          // persistent kernel CTAs (1 per SM, all co-resident)
#define RTHREADS 128      // threads per persistent CTA
#define WPAD 260          // smem row stride in floats (mult of 4, bank-safe: 260%32==4)

// ---------------- device scratch (static: no allocations allowed) ----------------
__device__ float g_pre0[(size_t)Ssz * Bsz * Hsz];   // [s][b][h]  (512 MB)
__device__ float g_h0[2][Bsz * Hsz];                // double-buffered layer-0 state [b][h]
__device__ float g_h1[2][Bsz * Hsz];                // double-buffered layer-1 state [b][h]
__device__ volatile unsigned int g_flags[NCTA];     // per-CTA barrier arrival counters

// ---------------- init: zero state seed buffers + flags ----------------
__global__ void init_kernel() {
    int idx = blockIdx.x * blockDim.x + threadIdx.x;
    if (idx < Bsz * Hsz) {
        g_h0[1][idx] = 0.0f;   // "previous" buffer read at iteration 0
        g_h1[1][idx] = 0.0f;   // "previous" buffer read at iteration 1
    }
    if (idx < NCTA) g_flags[idx] = 0u;
}

// ---------------- pre0 = x @ W_ih0^T + (b_ih0 + b_hh0) ----------------
// grid: (Ssz, Bsz/16), 256 threads. Each block: 16 b-rows x 256 h-cols.
__global__ void pre0_kernel(const float* __restrict__ x,
                            const float* __restrict__ Wih0,
                            const float* __restrict__ bih0,
                            const float* __restrict__ bhh0) {
    __shared__ float sW[128 * 68];   // half of W_ih0: [h][k], padded (68%32==4 -> conflict-free LDS.128)
    __shared__ float sX[16 * 68];    // x tile: [r][k]

    const int s   = blockIdx.x;
    const int b0  = blockIdx.y * 16;
    const int tid = threadIdx.x;

    // load x tile: x[b][s][d]
    for (int i = tid; i < 16 * Dsz; i += 256) {
        int r = i >> 6, k = i & 63;
        sX[r * 68 + k] = x[((size_t)(b0 + r) * Ssz + s) * Dsz + k];
    }

    const int g  = tid >> 7;     // 0..1 : row group (8 rows each)
    const int hl = tid & 127;    // h within half

    for (int half = 0; half < 2; ++half) {
        __syncthreads();
        for (int i = tid; i < 128 * Dsz; i += 256) {
            int h = i >> 6, k = i & 63;
            sW[h * 68 + k] = Wih0[(size_t)(half * 128 + h) * Dsz + k];
        }
        __syncthreads();

        float acc[8];
#pragma unroll
        for (int r = 0; r < 8; ++r) acc[r] = 0.0f;

#pragma unroll 4
        for (int kq = 0; kq < Dsz / 4; ++kq) {
            float4 w = *(const float4*)(sW + hl * 68 + kq * 4);
#pragma unroll
            for (int r = 0; r < 8; ++r) {
                float4 xv = *(const float4*)(sX + (g * 8 + r) * 68 + kq * 4);
                acc[r] += w.x * xv.x + w.y * xv.y + w.z * xv.z + w.w * xv.w;
            }
        }

        const int hglob = half * 128 + hl;
        const float bsum = bih0[hglob] + bhh0[hglob];
#pragma unroll
        for (int r = 0; r < 8; ++r) {
            g_pre0[((size_t)s * Bsz + b0 + g * 8 + r) * Hsz + hglob] = acc[r] + bsum;
        }
    }
}

// ---------------- software grid barrier (per-CTA flag slots, no atomics) ----------------
// 128 CTAs, 128 threads: thread t polls CTA t's flag. Flags are monotonic within a launch.
__device__ __forceinline__ void grid_barrier(unsigned int val) {
    __threadfence();                 // release: each thread's global writes visible
    __syncthreads();                 // all threads of this CTA have fenced
    if (threadIdx.x == 0) g_flags[blockIdx.x] = val;
    while (g_flags[threadIdx.x] < val) { }   // volatile poll (L2)
    __threadfence();                 // acquire
    __syncthreads();
}

// ---------------- persistent fused recurrence ----------------
// 128 CTAs x 128 threads. CTA c: b-rows [16*(c>>3), +16), h-cols [32*(c&7), +32).
// Iteration i (0..S): computes h0_i (i<S) and h1_{i-1} (i>=1). One barrier per iteration.
__global__ void __launch_bounds__(RTHREADS, 1)
rnn_kernel(const float* __restrict__ Whh0,
           const float* __restrict__ Wih1,
           const float* __restrict__ Whh1,
           const float* __restrict__ bih1,
           const float* __restrict__ bhh1) {
    extern __shared__ float smem[];
    float* sW0  = smem;                    // [32][WPAD]  W_hh0 cols
    float* sWi1 = sW0  + 32 * WPAD;        // [32][WPAD]  W_ih1 cols
    float* sWh1 = sWi1 + 32 * WPAD;        // [32][WPAD]  W_hh1 cols
    float* sH0  = sWh1 + 32 * WPAD;        // [16][WPAD]  h0_{i-1} rows
    float* sH1  = sH0  + 16 * WPAD;        // [16][WPAD]  h1_{i-2} rows

    const int cta  = blockIdx.x;
    const int b0   = (cta >> 3) * 16;
    const int h0c  = (cta & 7) * 32;
    const int lane = threadIdx.x & 31;
    const int warp = threadIdx.x >> 5;     // 0..3
    const int r0   = warp * 4;             // 4 rows per warp

    // ---- load the three weight tiles once (32 cols x 256 k each) ----
    {
        const int col = threadIdx.x >> 2;          // 0..31
        const int kb  = (threadIdx.x & 3) * 64;    // 0/64/128/192
        const size_t grow = (size_t)(h0c + col) * Hsz + kb;
        const float4* gw0 = (const float4*)(Whh0 + grow);
        const float4* gw1 = (const float4*)(Wih1 + grow);
        const float4* gw2 = (const float4*)(Whh1 + grow);
        float4* d0 = (float4*)(sW0  + col * WPAD + kb);
        float4* d1 = (float4*)(sWi1 + col * WPAD + kb);
        float4* d2 = (float4*)(sWh1 + col * WPAD + kb);
#pragma unroll
        for (int q = 0; q < 16; ++q) { d0[q] = gw0[q]; d1[q] = gw1[q]; d2[q] = gw2[q]; }
    }
    const float bias1 = bih1[h0c + lane] + bhh1[h0c + lane];
    __syncthreads();

    const int hrow = threadIdx.x >> 3;         // 0..15
    const int hkb  = (threadIdx.x & 7) * 32;   // 8 segments of 32 floats

    for (int i = 0; i <= Ssz; ++i) {
        // ---- stage previous states into SMEM ----
        {
            const float* src = g_h0[(i + 1) & 1] + (size_t)(b0 + hrow) * Hsz + hkb;
            float4* dst = (float4*)(sH0 + hrow * WPAD + hkb);
#pragma unroll
            for (int q = 0; q < 8; ++q) dst[q] = ((const float4*)src)[q];
        }
        if (i >= 1) {
            const float* src = g_h1[i & 1] + (size_t)(b0 + hrow) * Hsz + hkb;
            float4* dst = (float4*)(sH1 + hrow * WPAD + hkb);
#pragma unroll
            for (int q = 0; q < 8; ++q) dst[q] = ((const float4*)src)[q];
        }
        __syncthreads();

        // ---- h0_i = tanh(pre0_i + h0_{i-1} @ Whh0^T) ----
        if (i < Ssz) {
            float p[4];
#pragma unroll
            for (int r = 0; r < 4; ++r)
                p[r] = g_pre0[((size_t)i * Bsz + b0 + r0 + r) * Hsz + h0c + lane];

            float a[4] = {0.f, 0.f, 0.f, 0.f};
#pragma unroll 4
            for (int kq = 0; kq < 64; ++kq) {
                float4 w = *(const float4*)(sW0 + lane * WPAD + kq * 4);
#pragma unroll
                for (int r = 0; r < 4; ++r) {
                    float4 xv = *(const float4*)(sH0 + (r0 + r) * WPAD + kq * 4);
                    a[r] += w.x * xv.x + w.y * xv.y + w.z * xv.z + w.w * xv.w;
                }
            }
            float* dst = g_h0[i & 1];
#pragma unroll
            for (int r = 0; r < 4; ++r)
                dst[(size_t)(b0 + r0 + r) * Hsz + h0c + lane] = tanhf(p[r] + a[r]);
        }

        // ---- h1_{i-1} = tanh(b1 + h0_{i-1} @ Wih1^T + h1_{i-2} @ Whh1^T) ----
        if (i >= 1) {
            float a[4] = {bias1, bias1, bias1, bias1};
#pragma unroll 4
            for (int kq = 0; kq < 64; ++kq) {
                float4 w = *(const float4*)(sWi1 + lane * WPAD + kq * 4);
#pragma unroll
                for (int r = 0; r < 4; ++r) {
                    float4 xv = *(const float4*)(sH0 + (r0 + r) * WPAD + kq * 4);
                    a[r] += w.x * xv.x + w.y * xv.y + w.z * xv.z + w.w * xv.w;
                }
            }
#pragma unroll 4
            for (int kq = 0; kq < 64; ++kq) {
                float4 w = *(const float4*)(sWh1 + lane * WPAD + kq * 4);
#pragma unroll
                for (int r = 0; r < 4; ++r) {
                    float4 xv = *(const float4*)(sH1 + (r0 + r) * WPAD + kq * 4);
                    a[r] += w.x * xv.x + w.y * xv.y + w.z * xv.z + w.w * xv.w;
                }
            }
            float* dst = g_h1[(i - 1) & 1];
#pragma unroll
            for (int r = 0; r < 4; ++r)
                dst[(size_t)(b0 + r0 + r) * Hsz + h0c + lane] = tanhf(a[r]);
        }

        grid_barrier((unsigned int)(i + 1));
    }
}

// ---------------- head: out = sigmoid(h1_last @ W_out^T + b_out) ----------------
// h1_last = h1_{S-1}, stored in buffer (S-1)&1 == 1.
__global__ void head_kernel(const float* __restrict__ Wout,
                            const float* __restrict__ bout,
                            float* __restrict__ out) {
    const int warp = threadIdx.x >> 5;
    const int lane = threadIdx.x & 31;
    const int b = blockIdx.x * 8 + warp;
    const float* h = g_h1[(Ssz - 1) & 1] + (size_t)b * Hsz;
    float s = 0.0f;
#pragma unroll
    for (int k = lane; k < Hsz; k += 32) s += h[k] * Wout[k];
#pragma unroll
    for (int o = 16; o > 0; o >>= 1) s += __shfl_down_sync(0xFFFFFFFFu, s, o);
    if (lane == 0) out[b] = 1.0f / (1.0f + expf(-(s + bout[0])));
}

// ---------------- launch ----------------
extern "C" void kernel_launch(void* const* d_in, const int* in_sizes, int n_in,
                              void* d_out, int out_size) {
    const float* x    = (const float*)d_in[0];
    const float* Wih0 = (const float*)d_in[1];
    const float* Whh0 = (const float*)d_in[2];
    const float* bih0 = (const float*)d_in[3];
    const float* bhh0 = (const float*)d_in[4];
    const float* Wih1 = (const float*)d_in[5];
    const float* Whh1 = (const float*)d_in[6];
    const float* bih1 = (const float*)d_in[7];
    const float* bhh1 = (const float*)d_in[8];
    const float* Wout = (const float*)d_in[9];
    const float* bout = (const float*)d_in[10];
    float* out = (float*)d_out;

    const int rnn_smem = (3 * 32 + 2 * 16) * WPAD * (int)sizeof(float); // 133120 B
    static int configured = 0;
    if (!configured) {
        cudaFuncSetAttribute(rnn_kernel, cudaFuncAttributeMaxDynamicSharedMemorySize, rnn_smem);
        configured = 1;
    }

    init_kernel<<<(Bsz * Hsz + 255) / 256, 256>>>();
    pre0_kernel<<<dim3(Ssz, Bsz / 16), 256>>>(x, Wih0, bih0, bhh0);
    rnn_kernel<<<NCTA, RTHREADS, rnn_smem>>>(Whh0, Wih1, Whh1, bih1, bhh1);
    head_kernel<<<Bsz / 8, 256>>>(Wout, bout, out);
}